// round 17
// baseline (speedup 1.0000x reference)
#include <cuda_runtime.h>
#include <math.h>

// BTNetEuropean closed form:
//   out[b] = sum_j C(N,j) w0^{N-j} w1^j * relu(k[b]*w_init[j] + b_init[j])
// x_j monotone decreasing in j => relu mask is a prefix:
//   out[b] = (k*PW[j*] + PB[j*]) * scale,  j* = #{j : x_j > 0}.
//
// R17 = R16 resubmit (infra flake): 128 blocks x 64 threads (2 warps),
// EPT=16. No smem staging of w_init/b_init: build reads its chunk from
// registers; verification probes go to GLOBAL, issued early (g depends only
// on kv/bi0/biN) so they complete under the scan. Pass 2 writes within-lane
// running prefixes to the smem table; fix-up pass adds scanned offsets.
// Mid-chunk renorm keeps the 16-ratio product inside fp32 range. Same
// E0-Stirling normalization + exact (w0+w1)^N/sum compensation as R13-R15.
// No __device__ state — fully deterministic.

#define N_DIM   1024
#define N_NODES 1025
#define BATCH   8192
#define NT      64
#define EPT     16         // table elements per thread (NT*EPT = 1024)

__global__ __launch_bounds__(NT)
void fused_kernel(const float* __restrict__ k,
                  const float* __restrict__ w_init,
                  const float* __restrict__ b_init,
                  const float* __restrict__ w,
                  float* __restrict__ out)
{
    __shared__ float s_Tw[N_NODES + 1];   // exclusive prefix of c*wi (+bw)
    __shared__ float s_Tb[N_NODES + 1];   // exclusive prefix of c*bi (+bb)
    __shared__ float s_m[2];
    __shared__ int   s_e[2];
    __shared__ float s_S[3][2];
    __shared__ float s_pw[2];
    __shared__ float s_scale;

    const int tid  = threadIdx.x;
    const int lane = tid & 31;
    const int wid  = tid >> 5;            // 0..1
    const unsigned FULL = 0xFFFFFFFFu;

    // ---- round 1: ALL global loads issued together ----
    const int   b   = blockIdx.x * NT + tid;      // 128 * 64 = BATCH
    const float kv  = __ldg(&k[b]);
    const float w0  = __ldg(&w[0]);
    const float w1  = __ldg(&w[1]);
    const float wi0 = __ldg(&w_init[0]);
    const float bi0 = __ldg(&b_init[0]);
    const float biN = __ldg(&b_init[N_DIM]);

    const int i0 = tid * EPT;                     // ratio indices i0..i0+15
    float wiL[EPT], biL[EPT];
    #pragma unroll
    for (int j = 0; j < EPT; j++) {
        wiL[j] = __ldg(&w_init[i0 + 1 + j]);
        biL[j] = __ldg(&b_init[i0 + 1 + j]);
    }

    const float rw = w1 / w0;

    // analytic normalizer E0 ~= log2(c_max/c_0) via Stirling (fp32);
    // only needs +-30 bits, exactly compensated by the final scale.
    float p    = rw / (1.0f + rw);
    float m0f  = rintf(1024.0f * p);
    float H2   = -p * log2f(p) - (1.0f - p) * log2f(1.0f - p);
    float l2C  = 1024.0f * H2
               - 0.5f * log2f(6.2831853f * 1024.0f * p * (1.0f - p));
    const int E0 = (int)(l2C + m0f * log2f(rw)) + 2;

    // analytic j* guess: ln(-b_init[j]) is affine in j
    float L0    = logf(-bi0);
    float LN    = logf(-biN);
    float slope = (LN - L0) * (1.0f / (float)N_DIM);
    float jf    = (logf(kv) - L0) / slope;
    int g;
    if (jf >= 0.0f) {                     // NaN-safe: NaN -> g = 0
        g = (jf >= (float)N_NODES) ? N_NODES : (int)ceilf(jf);
    } else {
        g = 0;
    }

    // EARLY probe loads (global; complete under the scan)
    float pw_g = 0.0f, pb_g = 0.0f, pw_m = 0.0f, pb_m = 0.0f;
    if (g < N_NODES) { pw_g = __ldg(&w_init[g]);     pb_g = __ldg(&b_init[g]); }
    if (g > 0)       { pw_m = __ldg(&w_init[g - 1]); pb_m = __ldg(&b_init[g - 1]); }

    // thread 0: (w0+w1)^1024 in double-float; publish before BAR1
    if (tid == 0) {
        float sh = w0 + w1;
        float sl = (w0 - sh) + w1;        // TwoSum error term
        #pragma unroll
        for (int i = 0; i < 10; i++) {    // df squaring x10
            float ph = sh * sh;
            float pe = fmaf(sh, sh, -ph);
            float pl = fmaf(2.0f * sh, sl, pe);
            float t  = ph + pl;
            pl = (ph - t) + pl;
            sh = t; sl = pl;
        }
        s_pw[0] = sh; s_pw[1] = sl;
    }

    // ---- Phase A: serial product of 16 ratios (renorm at 8), warp scan ----
    float rhoL[EPT];
    float P = 1.0f; int eP = 0;
    #pragma unroll
    for (int j = 0; j < EPT; j++) {
        int   i   = i0 + j;
        float rho = ((float)(N_DIM - i) / (float)(i + 1)) * rw;
        rhoL[j] = rho;
        P *= rho;
        if (j == 7) { int t; P = frexpf(P, &t); eP += t; }   // overflow guard
    }
    { int t; P = frexpf(P, &t); eP += t; }
    float m = P; int e = eP;

    // warp inclusive product scan of thread chunk products
    float mi = m; int ei = e;
    #pragma unroll
    for (int d = 1; d < 32; d <<= 1) {
        float mo = __shfl_up_sync(FULL, mi, d);
        int   eo = __shfl_up_sync(FULL, ei, d);
        if (lane >= d) {
            mi *= mo; ei += eo;
            if (mi < 0.5f) { mi *= 2.0f; ei -= 1; }
        }
    }
    float mex = __shfl_up_sync(FULL, mi, 1);      // exclusive-within-warp
    int   eex = __shfl_up_sync(FULL, ei, 1);
    if (lane == 0) { mex = 0.5f; eex = 1; }       // identity (1.0)
    if (lane == 31) { s_m[wid] = mi; s_e[wid] = ei; }   // warp totals
    __syncthreads();                               // BAR1

    // cross-warp exclusive product (warp 1 folds in warp 0's total)
    float Mc = mex; int Ec = eex;
    if (wid == 1) { Mc *= s_m[0]; Ec += s_e[0]; }
    { int t; Mc = frexpf(Mc, &t); Ec += t; }       // renormalize once

    // f = c_{i0} * 2^-E0 (exclusive product through ratio i0-1, normalized)
    const float f = ldexpf(Mc, Ec - E0);

    // ---- Phase B: pass 2 — running coefficient, write lane-local prefixes ----
    float c = f, t0 = 0.0f, r1 = 0.0f, r2 = 0.0f;
    #pragma unroll
    for (int j = 0; j < EPT; j++) {
        c  = c * rhoL[j];                  // chat_{i0+1+j} * 2^-E0
        t0 += c;
        r1 += c * wiL[j];
        r2 += c * biL[j];
        s_Tw[i0 + 2 + j] = r1;             // lane-local running prefix
        s_Tb[i0 + 2 + j] = r2;
    }
    const float t1 = r1, t2 = r2;

    // warp inclusive triple sum scan of lane totals
    float a0 = t0, a1 = t1, a2 = t2;
    #pragma unroll
    for (int d = 1; d < 32; d <<= 1) {
        float u0 = __shfl_up_sync(FULL, a0, d);
        float u1 = __shfl_up_sync(FULL, a1, d);
        float u2 = __shfl_up_sync(FULL, a2, d);
        if (lane >= d) { a0 += u0; a1 += u1; a2 += u2; }
    }
    if (lane == 31) { s_S[0][wid] = a0; s_S[1][wid] = a1; s_S[2][wid] = a2; }
    __syncthreads();                               // BAR2

    // exclusive offsets (cross-warp: warp 1 folds in warp 0's totals)
    float O0 = a0 - t0, O1 = a1 - t1, O2 = a2 - t2;
    if (wid == 1) { O0 += s_S[0][0]; O1 += s_S[1][0]; O2 += s_S[2][0]; }

    const float c0 = ldexpf(1.0f, -E0);   // chat_0 (usually flushes to 0)
    const float bw = c0 * wi0;
    const float bb = c0 * bi0;

    // fix-up: add global offset (+bw/bb) to this lane's table entries
    const float F1 = bw + O1, F2 = bb + O2;
    #pragma unroll
    for (int j = 0; j < EPT; j++) {
        s_Tw[i0 + 2 + j] += F1;
        s_Tb[i0 + 2 + j] += F2;
    }
    if (tid == 0) {
        s_Tw[0] = 0.0f; s_Tb[0] = 0.0f;
        s_Tw[1] = bw;   s_Tb[1] = bb;
    }
    if (tid == NT - 1) {
        float totC = c0 + O0 + t0;         // sum of all c~
        float q = s_pw[0] / totC;          // df-refined divide
        q += (fmaf(-q, totC, s_pw[0]) + s_pw[1]) / totC;
        s_scale = q;                       // scale = (w0+w1)^N / S
    }
    __syncthreads();                               // BAR3

    // ---- price: verify guess (probes already in registers) ----
    float xg  = (g <  N_NODES) ? fmaf(kv, pw_g, pb_g) : -1.0f;
    float xgm = (g > 0)        ? fmaf(kv, pw_m, pb_m) :  1.0f;

    // monotone fix-up (rarely iterates; correct for any monotone input)
    if (xg > 0.0f) {
        do { g++; } while (g < N_NODES &&
            fmaf(kv, __ldg(&w_init[g]), __ldg(&b_init[g])) > 0.0f);
    } else if (xgm <= 0.0f) {
        do { g--; } while (g > 0 &&
            fmaf(kv, __ldg(&w_init[g - 1]), __ldg(&b_init[g - 1])) <= 0.0f);
    }

    out[b] = fmaf(kv, s_Tw[g], s_Tb[g]) * s_scale;
}

extern "C" void kernel_launch(void* const* d_in, const int* in_sizes, int n_in,
                              void* d_out, int out_size)
{
    const float* k      = (const float*)d_in[0];   // (8192,)
    const float* w_init = (const float*)d_in[1];   // (1025,)
    const float* b_init = (const float*)d_in[2];   // (1025,)
    const float* w      = (const float*)d_in[3];   // (2,)
    float*       out    = (float*)d_out;           // (8192,)

    (void)in_sizes; (void)n_in; (void)out_size;

    fused_kernel<<<BATCH / NT, NT>>>(k, w_init, b_init, w, out);
}